// round 16
// baseline (speedup 1.0000x reference)
#include <cuda_runtime.h>
#include <cuda_bf16.h>
#include <cuda_fp16.h>
#include <math.h>
#include <stdint.h>

#define NN 64512
#define EE 1032192
#define DIN 84
#define DH 128
#define BB 64
#define TT 1008
#define SNAPC 12
#define SEGC 84
#define RSQRT128 0.08838834764831845f
#define ROWB 272    // 128 x16 dims + pad -> conflict-free ldmatrix
#define ROWB1 208   // 96 bf16 dims + pad
#define ADJCAP 64

// ---------------- device scratch ----------------
__device__ int   g_flag;
__device__ int   g_cnt[NN];
__device__ int   g_adjp[NN * ADJCAP];
__device__ __align__(256) uint32_t g_t1h[NN * 48];
__device__ __align__(256) uint32_t g_t1l[NN * 48];
__device__ float g_h1[NN * DH];
__device__ __align__(256) uint32_t g_t2h[NN * 64];
__device__ __align__(256) uint32_t g_t2l[NN * 64];
__device__ __align__(256) uint32_t g_w1h[128 * 48];
__device__ __align__(256) uint32_t g_w1l[128 * 48];
__device__ __align__(256) uint32_t g_w2h[128 * 64];
__device__ __align__(256) uint32_t g_w2l[128 * 64];
__device__ __align__(256) uint32_t g_h2f[NN * 64];   // h2 FP16 pairs (for QK^T)
__device__ __align__(256) uint32_t g_h2h[NN * 64];   // h2 BF16 hi pairs (for V)
__device__ __align__(256) uint32_t g_h2l[NN * 64];   // h2 BF16 lo-residual pairs
__device__ float g_ctx[NN * DH];
__device__ float g_mq[NN];               // diag score (static softmax shift, no margin)
__device__ float g_feat[BB * 6144];
__device__ float g_pre1[BB * 512];
__device__ float g_out1[BB * 512];
__device__ float g_pre2[BB * 32];

// ---------------- smem / mma helpers (baseline ISA only) ----------------
__device__ __forceinline__ uint32_t smem_u32(const void* p) {
    uint32_t a;
    asm("{ .reg .u64 t; cvta.to.shared.u64 t, %1; cvt.u32.u64 %0, t; }"
        : "=r"(a) : "l"(p));
    return a;
}
#define CP16(d, s) \
    asm volatile("cp.async.cg.shared.global [%0], [%1], 16;" :: "r"(d), "l"(s) : "memory")
#define CP_COMMIT() asm volatile("cp.async.commit_group;" ::: "memory")
#define CP_WAIT0()  asm volatile("cp.async.wait_group 0;" ::: "memory")
#define CP_WAIT1()  asm volatile("cp.async.wait_group 1;" ::: "memory")
#define STSZ(d) \
    asm volatile("st.shared.v4.u32 [%0], {%1,%1,%1,%1};" :: "r"(d), "r"(0u) : "memory")

__device__ __forceinline__ void ldsm_x4(uint32_t* r, uint32_t a) {
    asm volatile("ldmatrix.sync.aligned.m8n8.x4.shared.b16 {%0,%1,%2,%3}, [%4];"
                 : "=r"(r[0]), "=r"(r[1]), "=r"(r[2]), "=r"(r[3]) : "r"(a));
}
__device__ __forceinline__ void ldsm_x4t(uint32_t* r, uint32_t a) {
    asm volatile("ldmatrix.sync.aligned.m8n8.x4.trans.shared.b16 {%0,%1,%2,%3}, [%4];"
                 : "=r"(r[0]), "=r"(r[1]), "=r"(r[2]), "=r"(r[3]) : "r"(a));
}
__device__ __forceinline__ void mma_bf16(float* c, const uint32_t* a,
                                         uint32_t b0, uint32_t b1) {
    asm volatile("mma.sync.aligned.m16n8k16.row.col.f32.bf16.bf16.f32 "
                 "{%0,%1,%2,%3}, {%4,%5,%6,%7}, {%8,%9}, {%0,%1,%2,%3};"
                 : "+f"(c[0]), "+f"(c[1]), "+f"(c[2]), "+f"(c[3])
                 : "r"(a[0]), "r"(a[1]), "r"(a[2]), "r"(a[3]), "r"(b0), "r"(b1));
}
__device__ __forceinline__ void mma_f16(float* c, const uint32_t* a,
                                        uint32_t b0, uint32_t b1) {
    asm volatile("mma.sync.aligned.m16n8k16.row.col.f32.f16.f16.f32 "
                 "{%0,%1,%2,%3}, {%4,%5,%6,%7}, {%8,%9}, {%0,%1,%2,%3};"
                 : "+f"(c[0]), "+f"(c[1]), "+f"(c[2]), "+f"(c[3])
                 : "r"(a[0]), "r"(a[1]), "r"(a[2]), "r"(a[3]), "r"(b0), "r"(b1));
}
// split (a,b) into bf16 hi pair + bf16 residual pair
__device__ __forceinline__ void split2(float a, float b, uint32_t& hip, uint32_t& lop) {
    __nv_bfloat16 ha = __float2bfloat16_rn(a);
    __nv_bfloat16 hb = __float2bfloat16_rn(b);
    float ra = a - __bfloat162float(ha);
    float rb = b - __bfloat162float(hb);
    __nv_bfloat162 hh; hh.x = ha; hh.y = hb;
    __nv_bfloat162 ll = __floats2bfloat162_rn(ra, rb);
    hip = *(uint32_t*)&hh;
    lop = *(uint32_t*)&ll;
}

extern __shared__ char sm_raw[];

// ---------------- init: zero counters + detect + convert W to bf16 hi/lo ----------------
__global__ void k_init(const int* ei, const float* __restrict__ w1,
                       const float* __restrict__ w2) {
    int i = blockIdx.x * blockDim.x + threadIdx.x;
    if (i < NN) g_cnt[i] = 0;
    if (i < 128 * 48) {
        int nn = i & 127, kp = i >> 7;
        int k0 = 2 * kp;
        float a = (k0 < DIN)     ? w1[k0 * DH + nn]       : 0.f;
        float b = (k0 + 1 < DIN) ? w1[(k0 + 1) * DH + nn] : 0.f;
        uint32_t hp, lp;
        split2(a, b, hp, lp);
        g_w1h[nn * 48 + kp] = hp;
        g_w1l[nn * 48 + kp] = lp;
    }
    if (i < 128 * 64) {
        int nn = i & 127, kp = i >> 7;
        uint32_t hp, lp;
        split2(w2[2 * kp * DH + nn], w2[(2 * kp + 1) * DH + nn], hp, lp);
        g_w2h[nn * 64 + kp] = hp;
        g_w2l[nn * 64 + kp] = lp;
    }
    if (blockIdx.x == 0 && threadIdx.x == 0) {
        int f = 1;
        for (int k = 0; k < 32; k++) {
            if (ei[2 * k + 1] != 0) { f = 0; break; }
        }
        g_flag = f;
    }
}

// ---------------- padded-adjacency fill (single edge pass) ----------------
__global__ void k_fill(const int* ei) {
    int e = blockIdx.x * blockDim.x + threadIdx.x;
    if (e >= EE) return;
    int f = g_flag;
    int src = f ? ei[2 * e] : ei[e];
    int dst = f ? ei[2 * (EE + e)] : ei[EE + e];
    int p = atomicAdd(&g_cnt[dst], 1);
    if (p < ADJCAP) g_adjp[dst * ADJCAP + p] = src;
}

// ---------------- aggregation 1: t1 = x + sum_nbr x  -> bf16 hi/lo pairs ----------------
__global__ void k_agg1(const float* __restrict__ x) {
    int gt = blockIdx.x * blockDim.x + threadIdx.x;
    int n = gt >> 5;
    int lane = gt & 31;
    if (n >= NN) return;
    int dg = min(g_cnt[n], ADJCAP);
    const int* adj = g_adjp + n * ADJCAP;
    bool act = lane < 21;
    float4 acc = make_float4(0.f, 0.f, 0.f, 0.f);
    if (act) acc = *(const float4*)(x + (size_t)n * DIN + lane * 4);
    for (int j0 = 0; j0 < dg; j0 += 32) {
        int my = (j0 + lane < dg) ? adj[j0 + lane] : 0;
        int cnt = min(32, dg - j0);
        int j = 0;
        for (; j + 4 <= cnt; j += 4) {
            int s0 = __shfl_sync(0xffffffffu, my, j);
            int s1 = __shfl_sync(0xffffffffu, my, j + 1);
            int s2 = __shfl_sync(0xffffffffu, my, j + 2);
            int s3 = __shfl_sync(0xffffffffu, my, j + 3);
            if (act) {
                float4 f0 = *(const float4*)(x + (size_t)s0 * DIN + lane * 4);
                float4 f1 = *(const float4*)(x + (size_t)s1 * DIN + lane * 4);
                float4 f2 = *(const float4*)(x + (size_t)s2 * DIN + lane * 4);
                float4 f3 = *(const float4*)(x + (size_t)s3 * DIN + lane * 4);
                acc.x += (f0.x + f1.x) + (f2.x + f3.x);
                acc.y += (f0.y + f1.y) + (f2.y + f3.y);
                acc.z += (f0.z + f1.z) + (f2.z + f3.z);
                acc.w += (f0.w + f1.w) + (f2.w + f3.w);
            }
        }
        for (; j < cnt; j++) {
            int s = __shfl_sync(0xffffffffu, my, j);
            if (act) {
                float4 f = *(const float4*)(x + (size_t)s * DIN + lane * 4);
                acc.x += f.x; acc.y += f.y; acc.z += f.z; acc.w += f.w;
            }
        }
    }
    if (act) {
        uint32_t h0, l0, h1, l1;
        split2(acc.x, acc.y, h0, l0);
        split2(acc.z, acc.w, h1, l1);
        uint2 hv; hv.x = h0; hv.y = h1;
        uint2 lv; lv.x = l0; lv.y = l1;
        *(uint2*)&g_t1h[(size_t)n * 48 + 2 * lane] = hv;
        *(uint2*)&g_t1l[(size_t)n * 48 + 2 * lane] = lv;
    } else if (lane < 24) {
        uint2 z; z.x = 0; z.y = 0;
        *(uint2*)&g_t1h[(size_t)n * 48 + 2 * lane] = z;
        *(uint2*)&g_t1l[(size_t)n * 48 + 2 * lane] = z;
    }
}

// ---------------- aggregation 2: t2 = h1 + sum_nbr h1 -> bf16 hi/lo pairs ----------------
__global__ void k_agg2() {
    int gt = blockIdx.x * blockDim.x + threadIdx.x;
    int n = gt >> 5;
    int lane = gt & 31;
    if (n >= NN) return;
    int dg = min(g_cnt[n], ADJCAP);
    const int* adj = g_adjp + n * ADJCAP;
    float4 acc = *(const float4*)(g_h1 + (size_t)n * DH + lane * 4);
    for (int j0 = 0; j0 < dg; j0 += 32) {
        int my = (j0 + lane < dg) ? adj[j0 + lane] : 0;
        int cnt = min(32, dg - j0);
        int j = 0;
        for (; j + 4 <= cnt; j += 4) {
            int s0 = __shfl_sync(0xffffffffu, my, j);
            int s1 = __shfl_sync(0xffffffffu, my, j + 1);
            int s2 = __shfl_sync(0xffffffffu, my, j + 2);
            int s3 = __shfl_sync(0xffffffffu, my, j + 3);
            float4 f0 = *(const float4*)(g_h1 + (size_t)s0 * DH + lane * 4);
            float4 f1 = *(const float4*)(g_h1 + (size_t)s1 * DH + lane * 4);
            float4 f2 = *(const float4*)(g_h1 + (size_t)s2 * DH + lane * 4);
            float4 f3 = *(const float4*)(g_h1 + (size_t)s3 * DH + lane * 4);
            acc.x += (f0.x + f1.x) + (f2.x + f3.x);
            acc.y += (f0.y + f1.y) + (f2.y + f3.y);
            acc.z += (f0.z + f1.z) + (f2.z + f3.z);
            acc.w += (f0.w + f1.w) + (f2.w + f3.w);
        }
        for (; j < cnt; j++) {
            int s = __shfl_sync(0xffffffffu, my, j);
            float4 f = *(const float4*)(g_h1 + (size_t)s * DH + lane * 4);
            acc.x += f.x; acc.y += f.y; acc.z += f.z; acc.w += f.w;
        }
    }
    uint32_t h0, l0, h1, l1;
    split2(acc.x, acc.y, h0, l0);
    split2(acc.z, acc.w, h1, l1);
    uint2 hv; hv.x = h0; hv.y = h1;
    uint2 lv; lv.x = l0; lv.y = l1;
    *(uint2*)&g_t2h[(size_t)n * 64 + 2 * lane] = hv;
    *(uint2*)&g_t2l[(size_t)n * 64 + 2 * lane] = lv;
}

// ---------------- GIN GEMM 1 (HMMA, W-resident, cp.async pipelined) ----------------
__global__ void __launch_bounds__(256) k_gemm1_mma(const float* __restrict__ b1) {
    const uint32_t TB = 128 * ROWB1;
    uint32_t WH = smem_u32(sm_raw);
    uint32_t WL = WH + TB;
    uint32_t AB = WL + TB;
    int tid = threadIdx.x, w = tid >> 5, lane = tid & 31;
    int g = lane >> 2, t4 = lane & 3;
    int m0 = blockIdx.x * 512;

    for (int lin = tid; lin < 1536; lin += 256) {
        int nn = lin / 12, ch = lin % 12;
        CP16(WH + (uint32_t)nn * ROWB1 + ch * 16, (const char*)(g_w1h + nn * 48) + ch * 16);
        CP16(WL + (uint32_t)nn * ROWB1 + ch * 16, (const char*)(g_w1l + nn * 48) + ch * 16);
    }
    for (int lin = tid; lin < 1536; lin += 256) {
        int row = lin / 12, ch = lin % 12;
        CP16(AB + (uint32_t)row * ROWB1 + ch * 16,
             (const char*)(g_t1h + (size_t)(m0 + row) * 48) + ch * 16);
        CP16(AB + TB + (uint32_t)row * ROWB1 + ch * 16,
             (const char*)(g_t1l + (size_t)(m0 + row) * 48) + ch * 16);
    }
    CP_COMMIT();

    uint32_t bw = (uint32_t)((lane & 7) + ((lane >> 4) & 1) * 8) * ROWB1
                + ((lane & 8) ? 16 : 0);

    for (int tile = 0; tile < 4; tile++) {
        if (tile < 3) {
            uint32_t NA = AB + (uint32_t)((tile + 1) & 1) * 2 * TB;
            int base = m0 + (tile + 1) * 128;
            for (int lin = tid; lin < 1536; lin += 256) {
                int row = lin / 12, ch = lin % 12;
                CP16(NA + (uint32_t)row * ROWB1 + ch * 16,
                     (const char*)(g_t1h + (size_t)(base + row) * 48) + ch * 16);
                CP16(NA + TB + (uint32_t)row * ROWB1 + ch * 16,
                     (const char*)(g_t1l + (size_t)(base + row) * 48) + ch * 16);
            }
            CP_COMMIT();
            CP_WAIT1();
        } else {
            CP_WAIT0();
        }
        __syncthreads();

        uint32_t AH = AB + (uint32_t)(tile & 1) * 2 * TB;
        uint32_t AL = AH + TB;
        uint32_t af[6][4], al[6][4];
        {
            int r = (lane < 16) ? lane : lane - 16;
            int koff = (lane < 16) ? 0 : 16;
            uint32_t qa = AH + (uint32_t)(16 * w + r) * ROWB1 + koff;
            uint32_t qb = AL + (uint32_t)(16 * w + r) * ROWB1 + koff;
            #pragma unroll
            for (int ks = 0; ks < 6; ks++) {
                ldsm_x4(af[ks], qa + ks * 32);
                ldsm_x4(al[ks], qb + ks * 32);
            }
        }

        float cc[16][4];
        #pragma unroll
        for (int i = 0; i < 16; i++)
            #pragma unroll
            for (int j = 0; j < 4; j++) cc[i][j] = 0.f;

        #pragma unroll
        for (int jj = 0; jj < 8; jj++) {
            uint32_t offj = (uint32_t)(jj * 16) * ROWB1;
            #pragma unroll
            for (int ks = 0; ks < 6; ks++) {
                uint32_t rh[4], rl[4];
                ldsm_x4(rh, WH + bw + offj + ks * 32);
                ldsm_x4(rl, WL + bw + offj + ks * 32);
                mma_bf16(cc[2 * jj],     af[ks], rh[0], rh[1]);
                mma_bf16(cc[2 * jj],     af[ks], rl[0], rl[1]);
                mma_bf16(cc[2 * jj],     al[ks], rh[0], rh[1]);
                mma_bf16(cc[2 * jj + 1], af[ks], rh[2], rh[3]);
                mma_bf16(cc[2 * jj + 1], af[ks], rl[2], rl[3]);
                mma_bf16(cc[2 * jj + 1], al[ks], rh[2], rh[3]);
            }
        }

        int row0 = m0 + tile * 128 + 16 * w + g, row1 = row0 + 8;
        #pragma unroll
        for (int jj = 0; jj < 8; jj++) {
            int c0 = jj * 16 + 2 * t4, c1 = c0 + 8;
            float2 v;
            v.x = cc[2 * jj][0] + b1[c0];     v.y = cc[2 * jj][1] + b1[c0 + 1];
            *(float2*)&g_h1[(size_t)row0 * DH + c0] = v;
            v.x = cc[2 * jj][2] + b1[c0];     v.y = cc[2 * jj][3] + b1[c0 + 1];
            *(float2*)&g_h1[(size_t)row1 * DH + c0] = v;
            v.x = cc[2 * jj + 1][0] + b1[c1]; v.y = cc[2 * jj + 1][1] + b1[c1 + 1];
            *(float2*)&g_h1[(size_t)row0 * DH + c1] = v;
            v.x = cc[2 * jj + 1][2] + b1[c1]; v.y = cc[2 * jj + 1][3] + b1[c1 + 1];
            *(float2*)&g_h1[(size_t)row1 * DH + c1] = v;
        }
        __syncthreads();
    }
}

// ---------------- GIN GEMM 2: writes FP16 + BF16 hi/lo + diag Mq ----------------
__global__ void __launch_bounds__(256) k_gemm2_mma(const float* __restrict__ b2,
                                                   const float* __restrict__ pe) {
    const uint32_t TB = 128 * ROWB;
    uint32_t WH = smem_u32(sm_raw);
    uint32_t WL = WH + TB;
    uint32_t AB = WL + TB;
    int tid = threadIdx.x, w = tid >> 5, lane = tid & 31;
    int g = lane >> 2, t4 = lane & 3;
    int m0 = blockIdx.x * 512;

    for (int lin = tid; lin < 2048; lin += 256) {
        int nn = lin >> 4, ch = lin & 15;
        CP16(WH + (uint32_t)nn * ROWB + ch * 16, (const char*)(g_w2h + nn * 64) + ch * 16);
        CP16(WL + (uint32_t)nn * ROWB + ch * 16, (const char*)(g_w2l + nn * 64) + ch * 16);
    }
    for (int lin = tid; lin < 2048; lin += 256) {
        int row = lin >> 4, ch = lin & 15;
        CP16(AB + (uint32_t)row * ROWB + ch * 16,
             (const char*)(g_t2h + (size_t)(m0 + row) * 64) + ch * 16);
        CP16(AB + TB + (uint32_t)row * ROWB + ch * 16,
             (const char*)(g_t2l + (size_t)(m0 + row) * 64) + ch * 16);
    }
    CP_COMMIT();

    uint32_t bw = (uint32_t)((lane & 7) + ((lane >> 4) & 1) * 8) * ROWB
                + ((lane & 8) ? 16 : 0);

    for (int tile = 0; tile < 4; tile++) {
        if (tile < 3) {
            uint32_t NA = AB + (uint32_t)((tile + 1) & 1) * 2 * TB;
            int base = m0 + (tile + 1) * 128;
            for (int lin = tid; lin < 2048; lin += 256) {
                int row = lin >> 4, ch = lin & 15;
                CP16(NA + (uint32_t)row * ROWB + ch * 16,
                     (const char*)(g_t2h + (size_t)(base + row) * 64) + ch * 16);
                CP16(NA + TB + (uint32_t)row * ROWB + ch * 16,
                     (const char*)(g_t2l + (size_t)(base + row) * 64) + ch * 16);
            }
            CP_COMMIT();
            CP_WAIT1();
        } else {
            CP_WAIT0();
        }
        __syncthreads();

        uint32_t AH = AB + (uint32_t)(tile & 1) * 2 * TB;
        uint32_t AL = AH + TB;
        uint32_t af[8][4], al[8][4];
        {
            int r = (lane < 16) ? lane : lane - 16;
            int koff = (lane < 16) ? 0 : 16;
            uint32_t qa = AH + (uint32_t)(16 * w + r) * ROWB + koff;
            uint32_t qb = AL + (uint32_t)(16 * w + r) * ROWB + koff;
            #pragma unroll
            for (int ks = 0; ks < 8; ks++) {
                ldsm_x4(af[ks], qa + ks * 32);
                ldsm_x4(al[ks], qb + ks * 32);
            }
        }

        float cc[16][4];
        #pragma unroll
        for (int i = 0; i < 16; i++)
            #pragma unroll
            for (int j = 0; j < 4; j++) cc[i][j] = 0.f;

        #pragma unroll
        for (int jj = 0; jj < 8; jj++) {
            uint32_t offj = (uint32_t)(jj * 16) * ROWB;
            #pragma unroll
            for (int ks = 0; ks < 8; ks++) {
                uint32_t rh[4], rl[4];
                ldsm_x4(rh, WH + bw + offj + ks * 32);
                ldsm_x4(rl, WL + bw + offj + ks * 32);
                mma_bf16(cc[2 * jj],     af[ks], rh[0], rh[1]);
                mma_bf16(cc[2 * jj],     af[ks], rl[0], rl[1]);
                mma_bf16(cc[2 * jj],     al[ks], rh[0], rh[1]);
                mma_bf16(cc[2 * jj + 1], af[ks], rh[2], rh[3]);
                mma_bf16(cc[2 * jj + 1], af[ks], rl[2], rl[3]);
                mma_bf16(cc[2 * jj + 1], al[ks], rh[2], rh[3]);
            }
        }

        int row0 = m0 + tile * 128 + 16 * w + g, row1 = row0 + 8;
        int p0 = row0 % TT, p1 = row1 % TT;
        float sq0 = 0.f, sq1 = 0.f;
        #pragma unroll
        for (int jj = 0; jj < 8; jj++) {
            int c0 = jj * 16 + 2 * t4, c1 = c0 + 8;
            float2 v;
            uint32_t hp, lp;
            __half2 hf;
            v.x = cc[2 * jj][0] + b2[c0] + pe[p0 * DH + c0];
            v.y = cc[2 * jj][1] + b2[c0 + 1] + pe[p0 * DH + c0 + 1];
            sq0 += v.x * v.x + v.y * v.y;
            split2(v.x, v.y, hp, lp);
            hf = __floats2half2_rn(v.x, v.y);
            g_h2f[(size_t)row0 * 64 + (c0 >> 1)] = *(uint32_t*)&hf;
            g_h2h[(size_t)row0 * 64 + (c0 >> 1)] = hp;
            g_h2l[(size_t)row0 * 64 + (c0 >> 1)] = lp;
            v.x = cc[2 * jj][2] + b2[c0] + pe[p1 * DH + c0];
            v.y = cc[2 * jj][3] + b2[c0 + 1] + pe[p1 * DH + c0 + 1];
            sq1 += v.x * v.x + v.y * v.y;
            split2(v.x, v.y, hp, lp);
            hf = __floats2half2_rn(v.x, v.y);
            g_h2f[(size_t)row1 * 64 + (c0 >> 1)] = *(uint32_t*)&hf;
            g_h2h[(size_t)row1 * 64 + (c0 >> 1)] = hp;
            g_h2l[(size_t)row1 * 64 + (c0 >> 1)] = lp;
            v.x = cc[2 * jj + 1][0] + b2[c1] + pe[p0 * DH + c1];
            v.y = cc[2 * jj + 1][1] + b2[c1 + 1] + pe[p0 * DH + c1 + 1];
            sq0 += v.x * v.x + v.y * v.y;
            split2(v.x, v.y, hp, lp);
            hf = __floats2half2_rn(v.x, v.y);
            g_h2f[(size_t)row0 * 64 + (c1 >> 1)] = *(uint32_t*)&hf;
            g_h2h[(size_t)row0 * 64 + (c1 >> 1)] = hp;
            g_h2l[(size_t)row0 * 64 + (c1 >> 1)] = lp;
            v.x = cc[2 * jj + 1][2] + b2[c1] + pe[p1 * DH + c1];
            v.y = cc[2 * jj + 1][3] + b2[c1 + 1] + pe[p1 * DH + c1 + 1];
            sq1 += v.x * v.x + v.y * v.y;
            split2(v.x, v.y, hp, lp);
            hf = __floats2half2_rn(v.x, v.y);
            g_h2f[(size_t)row1 * 64 + (c1 >> 1)] = *(uint32_t*)&hf;
            g_h2h[(size_t)row1 * 64 + (c1 >> 1)] = hp;
            g_h2l[(size_t)row1 * 64 + (c1 >> 1)] = lp;
        }
        sq0 += __shfl_xor_sync(0xffffffffu, sq0, 1);
        sq0 += __shfl_xor_sync(0xffffffffu, sq0, 2);
        sq1 += __shfl_xor_sync(0xffffffffu, sq1, 1);
        sq1 += __shfl_xor_sync(0xffffffffu, sq1, 2);
        if (t4 == 0) {
            g_mq[row0] = sq0 * RSQRT128;    // diag shift, no margin (bf16 P range OK)
            g_mq[row1] = sq1 * RSQRT128;
        }
        __syncthreads();
    }
}

// ---------------- attention tile staging (cp.async): fp16 K + bf16 V hi/lo ----------------
__device__ __forceinline__ void attn_stage3(uint32_t KF, uint32_t KH, uint32_t KL,
                                            const uint32_t* H2F, const uint32_t* H2H,
                                            const uint32_t* H2L, int base_row, int tid) {
    for (int lin = tid; lin < 2048; lin += 256) {
        int key = lin >> 4, ch = lin & 15;
        int gk = base_row + key;
        uint32_t dF = KF + (uint32_t)key * ROWB + ch * 16;
        uint32_t dH = KH + (uint32_t)key * ROWB + ch * 16;
        uint32_t dL = KL + (uint32_t)key * ROWB + ch * 16;
        if (gk < TT) {
            CP16(dF, (const char*)(H2F + (size_t)gk * 64) + ch * 16);
            CP16(dH, (const char*)(H2H + (size_t)gk * 64) + ch * 16);
            CP16(dL, (const char*)(H2L + (size_t)gk * 64) + ch * 16);
        } else {
            STSZ(dF);
            STSZ(dH);
            STSZ(dL);
        }
    }
}

// ---------------- flash attention: fp16 QK^T (single term) + bf16 P*V (hi/lo) ----------------
__global__ void __launch_bounds__(256) k_attn_mma() {
    uint32_t B0 = smem_u32(sm_raw);
    const uint32_t BUFSZ = 128 * ROWB;
    int tid = threadIdx.x, w = tid >> 5, lane = tid & 31;
    int g = lane >> 2, t = lane & 3;
    int b = blockIdx.y, q0 = blockIdx.x * 128;
    const uint32_t* H2F = g_h2f + (size_t)b * TT * 64;
    const uint32_t* H2H = g_h2h + (size_t)b * TT * 64;
    const uint32_t* H2L = g_h2l + (size_t)b * TT * 64;

    // stage Q (fp16 only) into buffer 0
    for (int lin = tid; lin < 2048; lin += 256) {
        int row = lin >> 4, ch = lin & 15;
        int q = q0 + row;
        uint32_t d = B0 + (uint32_t)row * ROWB + ch * 16;
        if (q < TT) CP16(d, (const char*)(H2F + (size_t)q * 64) + ch * 16);
        else        STSZ(d);
    }
    CP_COMMIT();
    CP_WAIT0();
    __syncthreads();

    uint32_t qf[8][4];
    {
        int r = (lane < 16) ? lane : lane - 16;
        int koff = (lane < 16) ? 0 : 16;
        uint32_t qa = B0 + (uint32_t)(16 * w + r) * ROWB + koff;
        #pragma unroll
        for (int ks = 0; ks < 8; ks++) ldsm_x4(qf[ks], qa + ks * 32);
    }
    __syncthreads();

    int row0 = q0 + 16 * w + g;
    float Mq0 = (row0 < TT) ? g_mq[b * TT + row0] : 0.f;
    float Mq1 = (row0 + 8 < TT) ? g_mq[b * TT + row0 + 8] : 0.f;
    float lsum0 = 0.f, lsum1 = 0.f;
    float cc[16][4];
    #pragma unroll
    for (int d = 0; d < 16; d++)
        #pragma unroll
        for (int i = 0; i < 4; i++) cc[d][i] = 0.f;

    uint32_t bwo = (uint32_t)((lane & 7) + ((lane >> 4) & 1) * 8) * ROWB
                 + ((lane & 8) ? 16 : 0);
    uint32_t vwo = (uint32_t)(lane & 15) * ROWB + (uint32_t)(lane >> 4) * 16;

    // prefetch tile 0 into buffer set 0
    attn_stage3(B0, B0 + BUFSZ, B0 + 2 * BUFSZ, H2F, H2H, H2L, 0, tid);
    CP_COMMIT();

    for (int kt = 0; kt < 8; kt++) {
        uint32_t KF = B0 + (uint32_t)(kt & 1) * 3 * BUFSZ;
        uint32_t KH = KF + BUFSZ;
        uint32_t KL = KF + 2 * BUFSZ;
        if (kt < 7) {
            uint32_t NF = B0 + (uint32_t)((kt + 1) & 1) * 3 * BUFSZ;
            attn_stage3(NF, NF + BUFSZ, NF + 2 * BUFSZ, H2F, H2H, H2L,
                        (kt + 1) * 128, tid);
            CP_COMMIT();
            CP_WAIT1();
        } else {
            CP_WAIT0();
        }
        __syncthreads();

        // ---- QK^T (fp16, single term) + static-shift softmax + pack BF16 P ----
        uint32_t pf[8][4];
        #pragma unroll
        for (int jj = 0; jj < 8; jj++) {
            float s0[4] = {0.f, 0.f, 0.f, 0.f};
            float s1[4] = {0.f, 0.f, 0.f, 0.f};
            uint32_t offj = (uint32_t)(jj * 16) * ROWB;
            #pragma unroll
            for (int ks = 0; ks < 8; ks++) {
                uint32_t rf[4];
                ldsm_x4(rf, KF + bwo + offj + ks * 32);
                mma_f16(s0, qf[ks], rf[0], rf[1]);
                mma_f16(s1, qf[ks], rf[2], rf[3]);
            }
            int c0 = kt * 128 + jj * 16 + 2 * t;
            float pg0 = (c0 < TT)     ? __expf(s0[0] * RSQRT128 - Mq0) : 0.f;
            float pg1 = (c0 + 1 < TT) ? __expf(s0[1] * RSQRT128 - Mq0) : 0.f;
            float ph0 = (c0 < TT)     ? __expf(s0[2] * RSQRT128 - Mq1) : 0.f;
            float ph1 = (c0 + 1 < TT) ? __expf(s0[3] * RSQRT128 - Mq1) : 0.f;
            float pg8 = (c0 + 8 < TT) ? __expf(s1[0] * RSQRT128 - Mq0) : 0.f;
            float pg9 = (c0 + 9 < TT) ? __expf(s1[1] * RSQRT128 - Mq0) : 0.f;
            float ph8 = (c0 + 8 < TT) ? __expf(s1[2] * RSQRT128 - Mq1) : 0.f;
            float ph9 = (c0 + 9 < TT) ? __expf(s1[3] * RSQRT128 - Mq1) : 0.f;
            __nv_bfloat162 t0 = __floats2bfloat162_rn(pg0, pg1);
            __nv_bfloat162 t1 = __floats2bfloat162_rn(ph0, ph1);
            __nv_bfloat162 t2 = __floats2bfloat162_rn(pg8, pg9);
            __nv_bfloat162 t3 = __floats2bfloat162_rn(ph8, ph9);
            pf[jj][0] = *(uint32_t*)&t0;
            pf[jj][1] = *(uint32_t*)&t1;
            pf[jj][2] = *(uint32_t*)&t2;
            pf[jj][3] = *(uint32_t*)&t3;
            // row sums from ROUNDED P values (cancellation in ctx ratio)
            lsum0 += __bfloat162float(t0.x) + __bfloat162float(t0.y)
                   + __bfloat162float(t2.x) + __bfloat162float(t2.y);
            lsum1 += __bfloat162float(t1.x) + __bfloat162float(t1.y)
                   + __bfloat162float(t3.x) + __bfloat162float(t3.y);
        }

        // ---- ctx += P * (Vhi + Vlo), bf16, streaming ----
        #pragma unroll
        for (int kk = 0; kk < 8; kk++) {
            uint32_t vbase = vwo + (uint32_t)(kk * 16) * ROWB;
            #pragma unroll
            for (int d = 0; d < 8; d++) {
                uint32_t vh[4], vl[4];
                ldsm_x4t(vh, KH + vbase + d * 32);
                ldsm_x4t(vl, KL + vbase + d * 32);
                mma_bf16(cc[2 * d],     pf[kk], vh[0], vh[1]);
                mma_bf16(cc[2 * d],     pf[kk], vl[0], vl[1]);
                mma_bf16(cc[2 * d + 1], pf[kk], vh[2], vh[3]);
                mma_bf16(cc[2 * d + 1], pf[kk], vl[2], vl[3]);
            }
        }
        __syncthreads();
    }

    lsum0 += __shfl_xor_sync(0xffffffffu, lsum0, 1);
    lsum0 += __shfl_xor_sync(0xffffffffu, lsum0, 2);
    lsum1 += __shfl_xor_sync(0xffffffffu, lsum1, 1);
    lsum1 += __shfl_xor_sync(0xffffffffu, lsum1, 2);
    float inv0 = 1.f / lsum0, inv1 = 1.f / lsum1;

    #pragma unroll
    for (int d = 0; d < 16; d++) {
        if (row0 < TT) {
            float2 v = make_float2(cc[d][0] * inv0, cc[d][1] * inv0);
            *(float2*)(g_ctx + ((size_t)b * TT + row0) * DH + d * 8 + 2 * t) = v;
        }
        if (row0 + 8 < TT) {
            float2 v = make_float2(cc[d][2] * inv1, cc[d][3] * inv1);
            *(float2*)(g_ctx + ((size_t)b * TT + row0 + 8) * DH + d * 8 + 2 * t) = v;
        }
    }
}

// ---------------- segmented max/mean pooling (+ zero pre1) ----------------
__global__ void k_pool() {
    if (blockIdx.x < 256) g_pre1[blockIdx.x * 128 + threadIdx.x] = 0.f;
    int b = blockIdx.x / SNAPC;
    int s = blockIdx.x % SNAPC;
    int d = threadIdx.x;
    size_t base = ((size_t)b * TT + s * SEGC) * DH + d;
    float mx1 = -1e30f, sm1 = 0.f, mx2 = -1e30f, sm2 = 0.f;
    for (int i = 0; i < SEGC; i++) {
        float v1 = g_h1[base + (size_t)i * DH];
        mx1 = fmaxf(mx1, v1); sm1 += v1;
        float v2 = g_ctx[base + (size_t)i * DH];
        mx2 = fmaxf(mx2, v2); sm2 += v2;
    }
    int o = b * 6144 + s * 512 + d;
    const float inv = 1.f / (float)SEGC;
    g_feat[o]       = mx1;
    g_feat[o + 128] = sm1 * inv;
    g_feat[o + 256] = mx2;
    g_feat[o + 384] = sm2 * inv;
}

// ---------------- MLP1 (split-K) ----------------
__global__ void k_mlp1(const float* __restrict__ wf1) {
    __shared__ float As[64][65];
    __shared__ float Bs[64][64];
    int tid = threadIdx.x;
    int tx = tid % 16, ty = tid / 16;
    int col0 = blockIdx.x * 64;
    int kbase = blockIdx.y * 512;
    float acc[4][4];
    #pragma unroll
    for (int i = 0; i < 4; i++)
        #pragma unroll
        for (int j = 0; j < 4; j++) acc[i][j] = 0.f;

    for (int kc = 0; kc < 8; kc++) {
        int kb = kbase + kc * 64;
        for (int lin = tid; lin < 4096; lin += 256) {
            int i = lin >> 6, j = lin & 63;
            As[i][j] = g_feat[i * 6144 + kb + j];
        }
        for (int lin = tid; lin < 4096; lin += 256) {
            int r = lin >> 6, c = lin & 63;
            Bs[r][c] = wf1[(size_t)(kb + r) * 512 + col0 + c];
        }
        __syncthreads();
        #pragma unroll 4
        for (int k = 0; k < 64; k++) {
            float a[4], bb[4];
            #pragma unroll
            for (int i = 0; i < 4; i++) a[i] = As[ty * 4 + i][k];
            #pragma unroll
            for (int j = 0; j < 4; j++) bb[j] = Bs[k][tx * 4 + j];
            #pragma unroll
            for (int i = 0; i < 4; i++)
                #pragma unroll
                for (int j = 0; j < 4; j++) acc[i][j] += a[i] * bb[j];
        }
        __syncthreads();
    }
    #pragma unroll
    for (int i = 0; i < 4; i++)
        #pragma unroll
        for (int j = 0; j < 4; j++)
            atomicAdd(&g_pre1[(ty * 4 + i) * 512 + col0 + tx * 4 + j], acc[i][j]);
}

// ---------------- BN1 ----------------
__global__ void k_bn1(const float* __restrict__ bf1, const float* __restrict__ g1,
                      const float* __restrict__ be1) {
    int c = blockIdx.x * blockDim.x + threadIdx.x;
    if (c >= 512) return;
    float bias = bf1[c];
    float s = 0.f, s2 = 0.f;
    for (int r = 0; r < 64; r++) {
        float v = g_pre1[r * 512 + c] + bias;
        v = v / (1.f + __expf(-v));
        s += v; s2 += v * v;
    }
    float mu = s * (1.f / 64.f);
    float var = s2 * (1.f / 64.f) - mu * mu;
    float sc = g1[c] * rsqrtf(var + 1e-5f);
    float sh = be1[c] - mu * sc;
    for (int r = 0; r < 64; r++) {
        float v = g_pre1[r * 512 + c] + bias;
        v = v / (1.f + __expf(-v));
        g_out1[r * 512 + c] = v * sc + sh;
    }
}

// ---------------- MLP2 ----------------
__global__ void k_mlp2(const float* __restrict__ wf2, const float* __restrict__ bf2) {
    int tid = threadIdx.x;
    int c = tid % 32;
    int r = blockIdx.x * 4 + tid / 32;
    const float* orow = g_out1 + r * 512;
    float acc = 0.f;
    for (int k = 0; k < 512; k++) acc += orow[k] * wf2[k * 32 + c];
    acc += bf2[c];
    g_pre2[r * 32 + c] = acc / (1.f + __expf(-acc));
}

// ---------------- head ----------------
__global__ void k_head(const float* __restrict__ g2, const float* __restrict__ be2,
                       const float* __restrict__ wf3, const float* __restrict__ bf3,
                       float* __restrict__ out) {
    __shared__ float sh[64 * 32];
    __shared__ float scale_s[32], shift_s[32];
    int tid = threadIdx.x;
    for (int i = tid; i < 2048; i += 256) sh[i] = g_pre2[i];
    __syncthreads();
    if (tid < 32) {
        int c = tid;
        float s = 0.f, s2 = 0.f;
        for (int r = 0; r < 64; r++) { float v = sh[r * 32 + c]; s += v; s2 += v * v; }
        float mu = s * (1.f / 64.f);
        float var = s2 * (1.f / 64.f) - mu * mu;
        float sc = g2[c] * rsqrtf(var + 1e-5f);
        scale_s[c] = sc;
        shift_s[c] = be2[c] - mu * sc;
    }
    __syncthreads();
    if (tid < 64) {
        int r = tid;
        float l0 = bf3[0], l1 = bf3[1];
        for (int c = 0; c < 32; c++) {
            float h = sh[r * 32 + c] * scale_s[c] + shift_s[c];
            l0 += h * wf3[c * 2];
            l1 += h * wf3[c * 2 + 1];
        }
        float m = fmaxf(l0, l1);
        float e0 = __expf(l0 - m), e1 = __expf(l1 - m);
        float inv = 1.f / (e0 + e1);
        out[r * 2]     = e0 * inv;
        out[r * 2 + 1] = e1 * inv;
    }
}

// ---------------- launcher ----------------
extern "C" void kernel_launch(void* const* d_in, const int* in_sizes, int n_in,
                              void* d_out, int out_size) {
    const float* x   = (const float*)d_in[0];
    const int*   ei  = (const int*)d_in[1];
    const float* w1  = (const float*)d_in[2];
    const float* b1  = (const float*)d_in[3];
    const float* w2  = (const float*)d_in[4];
    const float* b2  = (const float*)d_in[5];
    const float* pe  = (const float*)d_in[6];
    const float* wf1 = (const float*)d_in[7];
    const float* bf1 = (const float*)d_in[8];
    const float* g1  = (const float*)d_in[9];
    const float* be1 = (const float*)d_in[10];
    const float* wf2 = (const float*)d_in[11];
    const float* bf2 = (const float*)d_in[12];
    const float* g2  = (const float*)d_in[13];
    const float* be2 = (const float*)d_in[14];
    const float* wf3 = (const float*)d_in[15];
    const float* bf3 = (const float*)d_in[16];
    float* out = (float*)d_out;

    const int ATTN_SMEM = 6 * 128 * ROWB;    // 208896 (2x triple buffers: fp16 K + bf16 V hi/lo)
    const int G1_SMEM   = 6 * 128 * ROWB1;   // 159744
    const int G2_SMEM   = 6 * 128 * ROWB;    // 208896
    static int attr_set = 0;
    if (!attr_set) {
        cudaFuncSetAttribute(k_attn_mma, cudaFuncAttributeMaxDynamicSharedMemorySize,
                             ATTN_SMEM);
        cudaFuncSetAttribute(k_gemm1_mma, cudaFuncAttributeMaxDynamicSharedMemorySize,
                             G1_SMEM);
        cudaFuncSetAttribute(k_gemm2_mma, cudaFuncAttributeMaxDynamicSharedMemorySize,
                             G2_SMEM);
        attr_set = 1;
    }

    k_init<<<252, 256>>>(ei, w1, w2);                 // 1
    k_fill<<<EE / 256, 256>>>(ei);                    // 2
    k_agg1<<<NN / 8, 256>>>(x);                       // 3
    k_gemm1_mma<<<126, 256, G1_SMEM>>>(b1);           // 4 <- profiled slot
    k_agg2<<<NN / 8, 256>>>();                        // 5
    k_gemm2_mma<<<126, 256, G2_SMEM>>>(b2, pe);       // 6
    k_attn_mma<<<dim3(8, BB), 256, ATTN_SMEM>>>();    // 7
    k_pool<<<BB * SNAPC, 128>>>();                    // 8
    k_mlp1<<<dim3(8, 12), 256>>>(wf1);                // 9
    k_bn1<<<2, 256>>>(bf1, g1, be1);                  // 10
    k_mlp2<<<16, 128>>>(wf2, bf2);                    // 11
    k_head<<<1, 256>>>(g2, be2, wf3, bf3, out);       // 12
}

// round 17
// speedup vs baseline: 1.4393x; 1.4393x over previous
#include <cuda_runtime.h>
#include <cuda_bf16.h>
#include <cuda_fp16.h>
#include <math.h>
#include <stdint.h>

#define NN 64512
#define EE 1032192
#define DIN 84
#define DH 128
#define BB 64
#define TT 1008
#define SNAPC 12
#define SEGC 84
#define RSQRT128 0.08838834764831845f
#define ROWB 272    // 128 x16 dims + pad -> conflict-free ldmatrix
#define ROWB1 208   // 96 bf16 dims + pad
#define ADJCAP 64

// ---------------- device scratch ----------------
__device__ int   g_flag;
__device__ int   g_cnt[NN];
__device__ int   g_adjp[NN * ADJCAP];
__device__ __align__(256) uint32_t g_t1h[NN * 48];
__device__ __align__(256) uint32_t g_t1l[NN * 48];
__device__ float g_h1[NN * DH];
__device__ __align__(256) uint32_t g_t2h[NN * 64];
__device__ __align__(256) uint32_t g_t2l[NN * 64];
__device__ __align__(256) uint32_t g_w1h[128 * 48];
__device__ __align__(256) uint32_t g_w1l[128 * 48];
__device__ __align__(256) uint32_t g_w2h[128 * 64];
__device__ __align__(256) uint32_t g_w2l[128 * 64];
__device__ __align__(256) uint32_t g_h2f[NN * 64];   // h2 FP16 pairs (for QK^T)
__device__ __align__(256) uint32_t g_h2h[NN * 64];   // h2 BF16 hi pairs (for V)
__device__ __align__(256) uint32_t g_h2l[NN * 64];   // h2 BF16 lo-residual pairs
__device__ float g_ctx[NN * DH];
__device__ float g_mq[NN];               // diag score (static softmax shift, no margin)
__device__ float g_feat[BB * 6144];
__device__ float g_pre1[BB * 512];
__device__ float g_out1[BB * 512];
__device__ float g_pre2[BB * 32];

// ---------------- smem / mma helpers (baseline ISA only) ----------------
__device__ __forceinline__ uint32_t smem_u32(const void* p) {
    uint32_t a;
    asm("{ .reg .u64 t; cvta.to.shared.u64 t, %1; cvt.u32.u64 %0, t; }"
        : "=r"(a) : "l"(p));
    return a;
}
#define CP16(d, s) \
    asm volatile("cp.async.cg.shared.global [%0], [%1], 16;" :: "r"(d), "l"(s) : "memory")
#define CP_COMMIT() asm volatile("cp.async.commit_group;" ::: "memory")
#define CP_WAIT0()  asm volatile("cp.async.wait_group 0;" ::: "memory")
#define CP_WAIT1()  asm volatile("cp.async.wait_group 1;" ::: "memory")
#define STSZ(d) \
    asm volatile("st.shared.v4.u32 [%0], {%1,%1,%1,%1};" :: "r"(d), "r"(0u) : "memory")

__device__ __forceinline__ void ldsm_x4(uint32_t* r, uint32_t a) {
    asm volatile("ldmatrix.sync.aligned.m8n8.x4.shared.b16 {%0,%1,%2,%3}, [%4];"
                 : "=r"(r[0]), "=r"(r[1]), "=r"(r[2]), "=r"(r[3]) : "r"(a));
}
__device__ __forceinline__ void ldsm_x4t(uint32_t* r, uint32_t a) {
    asm volatile("ldmatrix.sync.aligned.m8n8.x4.trans.shared.b16 {%0,%1,%2,%3}, [%4];"
                 : "=r"(r[0]), "=r"(r[1]), "=r"(r[2]), "=r"(r[3]) : "r"(a));
}
__device__ __forceinline__ void mma_bf16(float* c, const uint32_t* a,
                                         uint32_t b0, uint32_t b1) {
    asm volatile("mma.sync.aligned.m16n8k16.row.col.f32.bf16.bf16.f32 "
                 "{%0,%1,%2,%3}, {%4,%5,%6,%7}, {%8,%9}, {%0,%1,%2,%3};"
                 : "+f"(c[0]), "+f"(c[1]), "+f"(c[2]), "+f"(c[3])
                 : "r"(a[0]), "r"(a[1]), "r"(a[2]), "r"(a[3]), "r"(b0), "r"(b1));
}
__device__ __forceinline__ void mma_f16(float* c, const uint32_t* a,
                                        uint32_t b0, uint32_t b1) {
    asm volatile("mma.sync.aligned.m16n8k16.row.col.f32.f16.f16.f32 "
                 "{%0,%1,%2,%3}, {%4,%5,%6,%7}, {%8,%9}, {%0,%1,%2,%3};"
                 : "+f"(c[0]), "+f"(c[1]), "+f"(c[2]), "+f"(c[3])
                 : "r"(a[0]), "r"(a[1]), "r"(a[2]), "r"(a[3]), "r"(b0), "r"(b1));
}
// split (a,b) into bf16 hi pair + bf16 residual pair
__device__ __forceinline__ void split2(float a, float b, uint32_t& hip, uint32_t& lop) {
    __nv_bfloat16 ha = __float2bfloat16_rn(a);
    __nv_bfloat16 hb = __float2bfloat16_rn(b);
    float ra = a - __bfloat162float(ha);
    float rb = b - __bfloat162float(hb);
    __nv_bfloat162 hh; hh.x = ha; hh.y = hb;
    __nv_bfloat162 ll = __floats2bfloat162_rn(ra, rb);
    hip = *(uint32_t*)&hh;
    lop = *(uint32_t*)&ll;
}

extern __shared__ char sm_raw[];

// ---------------- init: zero counters + detect + convert W to bf16 hi/lo ----------------
__global__ void k_init(const int* ei, const float* __restrict__ w1,
                       const float* __restrict__ w2) {
    int i = blockIdx.x * blockDim.x + threadIdx.x;
    if (i < NN) g_cnt[i] = 0;
    if (i < 128 * 48) {
        int nn = i & 127, kp = i >> 7;
        int k0 = 2 * kp;
        float a = (k0 < DIN)     ? w1[k0 * DH + nn]       : 0.f;
        float b = (k0 + 1 < DIN) ? w1[(k0 + 1) * DH + nn] : 0.f;
        uint32_t hp, lp;
        split2(a, b, hp, lp);
        g_w1h[nn * 48 + kp] = hp;
        g_w1l[nn * 48 + kp] = lp;
    }
    if (i < 128 * 64) {
        int nn = i & 127, kp = i >> 7;
        uint32_t hp, lp;
        split2(w2[2 * kp * DH + nn], w2[(2 * kp + 1) * DH + nn], hp, lp);
        g_w2h[nn * 64 + kp] = hp;
        g_w2l[nn * 64 + kp] = lp;
    }
    if (blockIdx.x == 0 && threadIdx.x == 0) {
        int f = 1;
        for (int k = 0; k < 32; k++) {
            if (ei[2 * k + 1] != 0) { f = 0; break; }
        }
        g_flag = f;
    }
}

// ---------------- padded-adjacency fill (single edge pass) ----------------
__global__ void k_fill(const int* ei) {
    int e = blockIdx.x * blockDim.x + threadIdx.x;
    if (e >= EE) return;
    int f = g_flag;
    int src = f ? ei[2 * e] : ei[e];
    int dst = f ? ei[2 * (EE + e)] : ei[EE + e];
    int p = atomicAdd(&g_cnt[dst], 1);
    if (p < ADJCAP) g_adjp[dst * ADJCAP + p] = src;
}

// ---------------- aggregation 1: t1 = x + sum_nbr x  -> bf16 hi/lo pairs ----------------
__global__ void k_agg1(const float* __restrict__ x) {
    int gt = blockIdx.x * blockDim.x + threadIdx.x;
    int n = gt >> 5;
    int lane = gt & 31;
    if (n >= NN) return;
    int dg = min(g_cnt[n], ADJCAP);
    const int* adj = g_adjp + n * ADJCAP;
    bool act = lane < 21;
    float4 acc = make_float4(0.f, 0.f, 0.f, 0.f);
    if (act) acc = *(const float4*)(x + (size_t)n * DIN + lane * 4);
    for (int j0 = 0; j0 < dg; j0 += 32) {
        int my = (j0 + lane < dg) ? adj[j0 + lane] : 0;
        int cnt = min(32, dg - j0);
        int j = 0;
        for (; j + 4 <= cnt; j += 4) {
            int s0 = __shfl_sync(0xffffffffu, my, j);
            int s1 = __shfl_sync(0xffffffffu, my, j + 1);
            int s2 = __shfl_sync(0xffffffffu, my, j + 2);
            int s3 = __shfl_sync(0xffffffffu, my, j + 3);
            if (act) {
                float4 f0 = *(const float4*)(x + (size_t)s0 * DIN + lane * 4);
                float4 f1 = *(const float4*)(x + (size_t)s1 * DIN + lane * 4);
                float4 f2 = *(const float4*)(x + (size_t)s2 * DIN + lane * 4);
                float4 f3 = *(const float4*)(x + (size_t)s3 * DIN + lane * 4);
                acc.x += (f0.x + f1.x) + (f2.x + f3.x);
                acc.y += (f0.y + f1.y) + (f2.y + f3.y);
                acc.z += (f0.z + f1.z) + (f2.z + f3.z);
                acc.w += (f0.w + f1.w) + (f2.w + f3.w);
            }
        }
        for (; j < cnt; j++) {
            int s = __shfl_sync(0xffffffffu, my, j);
            if (act) {
                float4 f = *(const float4*)(x + (size_t)s * DIN + lane * 4);
                acc.x += f.x; acc.y += f.y; acc.z += f.z; acc.w += f.w;
            }
        }
    }
    if (act) {
        uint32_t h0, l0, h1, l1;
        split2(acc.x, acc.y, h0, l0);
        split2(acc.z, acc.w, h1, l1);
        uint2 hv; hv.x = h0; hv.y = h1;
        uint2 lv; lv.x = l0; lv.y = l1;
        *(uint2*)&g_t1h[(size_t)n * 48 + 2 * lane] = hv;
        *(uint2*)&g_t1l[(size_t)n * 48 + 2 * lane] = lv;
    } else if (lane < 24) {
        uint2 z; z.x = 0; z.y = 0;
        *(uint2*)&g_t1h[(size_t)n * 48 + 2 * lane] = z;
        *(uint2*)&g_t1l[(size_t)n * 48 + 2 * lane] = z;
    }
}

// ---------------- aggregation 2: t2 = h1 + sum_nbr h1 -> bf16 hi/lo pairs ----------------
__global__ void k_agg2() {
    int gt = blockIdx.x * blockDim.x + threadIdx.x;
    int n = gt >> 5;
    int lane = gt & 31;
    if (n >= NN) return;
    int dg = min(g_cnt[n], ADJCAP);
    const int* adj = g_adjp + n * ADJCAP;
    float4 acc = *(const float4*)(g_h1 + (size_t)n * DH + lane * 4);
    for (int j0 = 0; j0 < dg; j0 += 32) {
        int my = (j0 + lane < dg) ? adj[j0 + lane] : 0;
        int cnt = min(32, dg - j0);
        int j = 0;
        for (; j + 4 <= cnt; j += 4) {
            int s0 = __shfl_sync(0xffffffffu, my, j);
            int s1 = __shfl_sync(0xffffffffu, my, j + 1);
            int s2 = __shfl_sync(0xffffffffu, my, j + 2);
            int s3 = __shfl_sync(0xffffffffu, my, j + 3);
            float4 f0 = *(const float4*)(g_h1 + (size_t)s0 * DH + lane * 4);
            float4 f1 = *(const float4*)(g_h1 + (size_t)s1 * DH + lane * 4);
            float4 f2 = *(const float4*)(g_h1 + (size_t)s2 * DH + lane * 4);
            float4 f3 = *(const float4*)(g_h1 + (size_t)s3 * DH + lane * 4);
            acc.x += (f0.x + f1.x) + (f2.x + f3.x);
            acc.y += (f0.y + f1.y) + (f2.y + f3.y);
            acc.z += (f0.z + f1.z) + (f2.z + f3.z);
            acc.w += (f0.w + f1.w) + (f2.w + f3.w);
        }
        for (; j < cnt; j++) {
            int s = __shfl_sync(0xffffffffu, my, j);
            float4 f = *(const float4*)(g_h1 + (size_t)s * DH + lane * 4);
            acc.x += f.x; acc.y += f.y; acc.z += f.z; acc.w += f.w;
        }
    }
    uint32_t h0, l0, h1, l1;
    split2(acc.x, acc.y, h0, l0);
    split2(acc.z, acc.w, h1, l1);
    uint2 hv; hv.x = h0; hv.y = h1;
    uint2 lv; lv.x = l0; lv.y = l1;
    *(uint2*)&g_t2h[(size_t)n * 64 + 2 * lane] = hv;
    *(uint2*)&g_t2l[(size_t)n * 64 + 2 * lane] = lv;
}

// ---------------- GIN GEMM 1 (HMMA, W-resident, cp.async pipelined) ----------------
__global__ void __launch_bounds__(256) k_gemm1_mma(const float* __restrict__ b1) {
    const uint32_t TB = 128 * ROWB1;
    uint32_t WH = smem_u32(sm_raw);
    uint32_t WL = WH + TB;
    uint32_t AB = WL + TB;
    int tid = threadIdx.x, w = tid >> 5, lane = tid & 31;
    int g = lane >> 2, t4 = lane & 3;
    int m0 = blockIdx.x * 512;

    for (int lin = tid; lin < 1536; lin += 256) {
        int nn = lin / 12, ch = lin % 12;
        CP16(WH + (uint32_t)nn * ROWB1 + ch * 16, (const char*)(g_w1h + nn * 48) + ch * 16);
        CP16(WL + (uint32_t)nn * ROWB1 + ch * 16, (const char*)(g_w1l + nn * 48) + ch * 16);
    }
    for (int lin = tid; lin < 1536; lin += 256) {
        int row = lin / 12, ch = lin % 12;
        CP16(AB + (uint32_t)row * ROWB1 + ch * 16,
             (const char*)(g_t1h + (size_t)(m0 + row) * 48) + ch * 16);
        CP16(AB + TB + (uint32_t)row * ROWB1 + ch * 16,
             (const char*)(g_t1l + (size_t)(m0 + row) * 48) + ch * 16);
    }
    CP_COMMIT();

    uint32_t bw = (uint32_t)((lane & 7) + ((lane >> 4) & 1) * 8) * ROWB1
                + ((lane & 8) ? 16 : 0);

    for (int tile = 0; tile < 4; tile++) {
        if (tile < 3) {
            uint32_t NA = AB + (uint32_t)((tile + 1) & 1) * 2 * TB;
            int base = m0 + (tile + 1) * 128;
            for (int lin = tid; lin < 1536; lin += 256) {
                int row = lin / 12, ch = lin % 12;
                CP16(NA + (uint32_t)row * ROWB1 + ch * 16,
                     (const char*)(g_t1h + (size_t)(base + row) * 48) + ch * 16);
                CP16(NA + TB + (uint32_t)row * ROWB1 + ch * 16,
                     (const char*)(g_t1l + (size_t)(base + row) * 48) + ch * 16);
            }
            CP_COMMIT();
            CP_WAIT1();
        } else {
            CP_WAIT0();
        }
        __syncthreads();

        uint32_t AH = AB + (uint32_t)(tile & 1) * 2 * TB;
        uint32_t AL = AH + TB;
        uint32_t af[6][4], al[6][4];
        {
            int r = (lane < 16) ? lane : lane - 16;
            int koff = (lane < 16) ? 0 : 16;
            uint32_t qa = AH + (uint32_t)(16 * w + r) * ROWB1 + koff;
            uint32_t qb = AL + (uint32_t)(16 * w + r) * ROWB1 + koff;
            #pragma unroll
            for (int ks = 0; ks < 6; ks++) {
                ldsm_x4(af[ks], qa + ks * 32);
                ldsm_x4(al[ks], qb + ks * 32);
            }
        }

        float cc[16][4];
        #pragma unroll
        for (int i = 0; i < 16; i++)
            #pragma unroll
            for (int j = 0; j < 4; j++) cc[i][j] = 0.f;

        #pragma unroll
        for (int jj = 0; jj < 8; jj++) {
            uint32_t offj = (uint32_t)(jj * 16) * ROWB1;
            #pragma unroll
            for (int ks = 0; ks < 6; ks++) {
                uint32_t rh[4], rl[4];
                ldsm_x4(rh, WH + bw + offj + ks * 32);
                ldsm_x4(rl, WL + bw + offj + ks * 32);
                mma_bf16(cc[2 * jj],     af[ks], rh[0], rh[1]);
                mma_bf16(cc[2 * jj],     af[ks], rl[0], rl[1]);
                mma_bf16(cc[2 * jj],     al[ks], rh[0], rh[1]);
                mma_bf16(cc[2 * jj + 1], af[ks], rh[2], rh[3]);
                mma_bf16(cc[2 * jj + 1], af[ks], rl[2], rl[3]);
                mma_bf16(cc[2 * jj + 1], al[ks], rh[2], rh[3]);
            }
        }

        int row0 = m0 + tile * 128 + 16 * w + g, row1 = row0 + 8;
        #pragma unroll
        for (int jj = 0; jj < 8; jj++) {
            int c0 = jj * 16 + 2 * t4, c1 = c0 + 8;
            float2 v;
            v.x = cc[2 * jj][0] + b1[c0];     v.y = cc[2 * jj][1] + b1[c0 + 1];
            *(float2*)&g_h1[(size_t)row0 * DH + c0] = v;
            v.x = cc[2 * jj][2] + b1[c0];     v.y = cc[2 * jj][3] + b1[c0 + 1];
            *(float2*)&g_h1[(size_t)row1 * DH + c0] = v;
            v.x = cc[2 * jj + 1][0] + b1[c1]; v.y = cc[2 * jj + 1][1] + b1[c1 + 1];
            *(float2*)&g_h1[(size_t)row0 * DH + c1] = v;
            v.x = cc[2 * jj + 1][2] + b1[c1]; v.y = cc[2 * jj + 1][3] + b1[c1 + 1];
            *(float2*)&g_h1[(size_t)row1 * DH + c1] = v;
        }
        __syncthreads();
    }
}

// ---------------- GIN GEMM 2: writes FP16 + BF16 hi/lo + diag Mq ----------------
__global__ void __launch_bounds__(256) k_gemm2_mma(const float* __restrict__ b2,
                                                   const float* __restrict__ pe) {
    const uint32_t TB = 128 * ROWB;
    uint32_t WH = smem_u32(sm_raw);
    uint32_t WL = WH + TB;
    uint32_t AB = WL + TB;
    int tid = threadIdx.x, w = tid >> 5, lane = tid & 31;
    int g = lane >> 2, t4 = lane & 3;
    int m0 = blockIdx.x * 512;

    for (int lin = tid; lin < 2048; lin += 256) {
        int nn = lin >> 4, ch = lin & 15;
        CP16(WH + (uint32_t)nn * ROWB + ch * 16, (const char*)(g_w2h + nn * 64) + ch * 16);
        CP16(WL + (uint32_t)nn * ROWB + ch * 16, (const char*)(g_w2l + nn * 64) + ch * 16);
    }
    for (int lin = tid; lin < 2048; lin += 256) {
        int row = lin >> 4, ch = lin & 15;
        CP16(AB + (uint32_t)row * ROWB + ch * 16,
             (const char*)(g_t2h + (size_t)(m0 + row) * 64) + ch * 16);
        CP16(AB + TB + (uint32_t)row * ROWB + ch * 16,
             (const char*)(g_t2l + (size_t)(m0 + row) * 64) + ch * 16);
    }
    CP_COMMIT();

    uint32_t bw = (uint32_t)((lane & 7) + ((lane >> 4) & 1) * 8) * ROWB
                + ((lane & 8) ? 16 : 0);

    for (int tile = 0; tile < 4; tile++) {
        if (tile < 3) {
            uint32_t NA = AB + (uint32_t)((tile + 1) & 1) * 2 * TB;
            int base = m0 + (tile + 1) * 128;
            for (int lin = tid; lin < 2048; lin += 256) {
                int row = lin >> 4, ch = lin & 15;
                CP16(NA + (uint32_t)row * ROWB + ch * 16,
                     (const char*)(g_t2h + (size_t)(base + row) * 64) + ch * 16);
                CP16(NA + TB + (uint32_t)row * ROWB + ch * 16,
                     (const char*)(g_t2l + (size_t)(base + row) * 64) + ch * 16);
            }
            CP_COMMIT();
            CP_WAIT1();
        } else {
            CP_WAIT0();
        }
        __syncthreads();

        uint32_t AH = AB + (uint32_t)(tile & 1) * 2 * TB;
        uint32_t AL = AH + TB;
        uint32_t af[8][4], al[8][4];
        {
            int r = (lane < 16) ? lane : lane - 16;
            int koff = (lane < 16) ? 0 : 16;
            uint32_t qa = AH + (uint32_t)(16 * w + r) * ROWB + koff;
            uint32_t qb = AL + (uint32_t)(16 * w + r) * ROWB + koff;
            #pragma unroll
            for (int ks = 0; ks < 8; ks++) {
                ldsm_x4(af[ks], qa + ks * 32);
                ldsm_x4(al[ks], qb + ks * 32);
            }
        }

        float cc[16][4];
        #pragma unroll
        for (int i = 0; i < 16; i++)
            #pragma unroll
            for (int j = 0; j < 4; j++) cc[i][j] = 0.f;

        #pragma unroll
        for (int jj = 0; jj < 8; jj++) {
            uint32_t offj = (uint32_t)(jj * 16) * ROWB;
            #pragma unroll
            for (int ks = 0; ks < 8; ks++) {
                uint32_t rh[4], rl[4];
                ldsm_x4(rh, WH + bw + offj + ks * 32);
                ldsm_x4(rl, WL + bw + offj + ks * 32);
                mma_bf16(cc[2 * jj],     af[ks], rh[0], rh[1]);
                mma_bf16(cc[2 * jj],     af[ks], rl[0], rl[1]);
                mma_bf16(cc[2 * jj],     al[ks], rh[0], rh[1]);
                mma_bf16(cc[2 * jj + 1], af[ks], rh[2], rh[3]);
                mma_bf16(cc[2 * jj + 1], af[ks], rl[2], rl[3]);
                mma_bf16(cc[2 * jj + 1], al[ks], rh[2], rh[3]);
            }
        }

        int row0 = m0 + tile * 128 + 16 * w + g, row1 = row0 + 8;
        int p0 = row0 % TT, p1 = row1 % TT;
        float sq0 = 0.f, sq1 = 0.f;
        #pragma unroll
        for (int jj = 0; jj < 8; jj++) {
            int c0 = jj * 16 + 2 * t4, c1 = c0 + 8;
            float2 v;
            uint32_t hp, lp;
            __half2 hf;
            v.x = cc[2 * jj][0] + b2[c0] + pe[p0 * DH + c0];
            v.y = cc[2 * jj][1] + b2[c0 + 1] + pe[p0 * DH + c0 + 1];
            sq0 += v.x * v.x + v.y * v.y;
            split2(v.x, v.y, hp, lp);
            hf = __floats2half2_rn(v.x, v.y);
            g_h2f[(size_t)row0 * 64 + (c0 >> 1)] = *(uint32_t*)&hf;
            g_h2h[(size_t)row0 * 64 + (c0 >> 1)] = hp;
            g_h2l[(size_t)row0 * 64 + (c0 >> 1)] = lp;
            v.x = cc[2 * jj][2] + b2[c0] + pe[p1 * DH + c0];
            v.y = cc[2 * jj][3] + b2[c0 + 1] + pe[p1 * DH + c0 + 1];
            sq1 += v.x * v.x + v.y * v.y;
            split2(v.x, v.y, hp, lp);
            hf = __floats2half2_rn(v.x, v.y);
            g_h2f[(size_t)row1 * 64 + (c0 >> 1)] = *(uint32_t*)&hf;
            g_h2h[(size_t)row1 * 64 + (c0 >> 1)] = hp;
            g_h2l[(size_t)row1 * 64 + (c0 >> 1)] = lp;
            v.x = cc[2 * jj + 1][0] + b2[c1] + pe[p0 * DH + c1];
            v.y = cc[2 * jj + 1][1] + b2[c1 + 1] + pe[p0 * DH + c1 + 1];
            sq0 += v.x * v.x + v.y * v.y;
            split2(v.x, v.y, hp, lp);
            hf = __floats2half2_rn(v.x, v.y);
            g_h2f[(size_t)row0 * 64 + (c1 >> 1)] = *(uint32_t*)&hf;
            g_h2h[(size_t)row0 * 64 + (c1 >> 1)] = hp;
            g_h2l[(size_t)row0 * 64 + (c1 >> 1)] = lp;
            v.x = cc[2 * jj + 1][2] + b2[c1] + pe[p1 * DH + c1];
            v.y = cc[2 * jj + 1][3] + b2[c1 + 1] + pe[p1 * DH + c1 + 1];
            sq1 += v.x * v.x + v.y * v.y;
            split2(v.x, v.y, hp, lp);
            hf = __floats2half2_rn(v.x, v.y);
            g_h2f[(size_t)row1 * 64 + (c1 >> 1)] = *(uint32_t*)&hf;
            g_h2h[(size_t)row1 * 64 + (c1 >> 1)] = hp;
            g_h2l[(size_t)row1 * 64 + (c1 >> 1)] = lp;
        }
        sq0 += __shfl_xor_sync(0xffffffffu, sq0, 1);
        sq0 += __shfl_xor_sync(0xffffffffu, sq0, 2);
        sq1 += __shfl_xor_sync(0xffffffffu, sq1, 1);
        sq1 += __shfl_xor_sync(0xffffffffu, sq1, 2);
        if (t4 == 0) {
            g_mq[row0] = sq0 * RSQRT128;    // diag shift, no margin (bf16 P range OK)
            g_mq[row1] = sq1 * RSQRT128;
        }
        __syncthreads();
    }
}

// ---------------- attention tile staging (cp.async): fp16 K + bf16 V hi/lo ----------------
__device__ __forceinline__ void attn_stage3(uint32_t KF, uint32_t KH, uint32_t KL,
                                            const uint32_t* H2F, const uint32_t* H2H,
                                            const uint32_t* H2L, int base_row, int tid) {
    for (int lin = tid; lin < 2048; lin += 256) {
        int key = lin >> 4, ch = lin & 15;
        int gk = base_row + key;
        uint32_t dF = KF + (uint32_t)key * ROWB + ch * 16;
        uint32_t dH = KH + (uint32_t)key * ROWB + ch * 16;
        uint32_t dL = KL + (uint32_t)key * ROWB + ch * 16;
        if (gk < TT) {
            CP16(dF, (const char*)(H2F + (size_t)gk * 64) + ch * 16);
            CP16(dH, (const char*)(H2H + (size_t)gk * 64) + ch * 16);
            CP16(dL, (const char*)(H2L + (size_t)gk * 64) + ch * 16);
        } else {
            STSZ(dF);
            STSZ(dH);
            STSZ(dL);
        }
    }
}

// ---------------- flash attention: fp16 QK^T (single term) + bf16 P*V (hi/lo) ----------------
__global__ void __launch_bounds__(256) k_attn_mma() {
    uint32_t B0 = smem_u32(sm_raw);
    const uint32_t BUFSZ = 128 * ROWB;
    int tid = threadIdx.x, w = tid >> 5, lane = tid & 31;
    int g = lane >> 2, t = lane & 3;
    int b = blockIdx.y, q0 = blockIdx.x * 128;
    const uint32_t* H2F = g_h2f + (size_t)b * TT * 64;
    const uint32_t* H2H = g_h2h + (size_t)b * TT * 64;
    const uint32_t* H2L = g_h2l + (size_t)b * TT * 64;

    // stage Q (fp16 only) into buffer 0
    for (int lin = tid; lin < 2048; lin += 256) {
        int row = lin >> 4, ch = lin & 15;
        int q = q0 + row;
        uint32_t d = B0 + (uint32_t)row * ROWB + ch * 16;
        if (q < TT) CP16(d, (const char*)(H2F + (size_t)q * 64) + ch * 16);
        else        STSZ(d);
    }
    CP_COMMIT();
    CP_WAIT0();
    __syncthreads();

    uint32_t qf[8][4];
    {
        int r = (lane < 16) ? lane : lane - 16;
        int koff = (lane < 16) ? 0 : 16;
        uint32_t qa = B0 + (uint32_t)(16 * w + r) * ROWB + koff;
        #pragma unroll
        for (int ks = 0; ks < 8; ks++) ldsm_x4(qf[ks], qa + ks * 32);
    }
    __syncthreads();

    int row0 = q0 + 16 * w + g;
    float Mq0 = (row0 < TT) ? g_mq[b * TT + row0] : 0.f;
    float Mq1 = (row0 + 8 < TT) ? g_mq[b * TT + row0 + 8] : 0.f;
    float lsum0 = 0.f, lsum1 = 0.f;
    float cc[16][4];
    #pragma unroll
    for (int d = 0; d < 16; d++)
        #pragma unroll
        for (int i = 0; i < 4; i++) cc[d][i] = 0.f;

    uint32_t bwo = (uint32_t)((lane & 7) + ((lane >> 4) & 1) * 8) * ROWB
                 + ((lane & 8) ? 16 : 0);
    uint32_t vwo = (uint32_t)(lane & 15) * ROWB + (uint32_t)(lane >> 4) * 16;

    // prefetch tile 0 into buffer set 0
    attn_stage3(B0, B0 + BUFSZ, B0 + 2 * BUFSZ, H2F, H2H, H2L, 0, tid);
    CP_COMMIT();

    for (int kt = 0; kt < 8; kt++) {
        uint32_t KF = B0 + (uint32_t)(kt & 1) * 3 * BUFSZ;
        uint32_t KH = KF + BUFSZ;
        uint32_t KL = KF + 2 * BUFSZ;
        if (kt < 7) {
            uint32_t NF = B0 + (uint32_t)((kt + 1) & 1) * 3 * BUFSZ;
            attn_stage3(NF, NF + BUFSZ, NF + 2 * BUFSZ, H2F, H2H, H2L,
                        (kt + 1) * 128, tid);
            CP_COMMIT();
            CP_WAIT1();
        } else {
            CP_WAIT0();
        }
        __syncthreads();

        // ---- QK^T (fp16, single term) + static-shift softmax + pack BF16 P ----
        uint32_t pf[8][4];
        #pragma unroll
        for (int jj = 0; jj < 8; jj++) {
            float s0[4] = {0.f, 0.f, 0.f, 0.f};
            float s1[4] = {0.f, 0.f, 0.f, 0.f};
            uint32_t offj = (uint32_t)(jj * 16) * ROWB;
            #pragma unroll
            for (int ks = 0; ks < 8; ks++) {
                uint32_t rf[4];
                ldsm_x4(rf, KF + bwo + offj + ks * 32);
                mma_f16(s0, qf[ks], rf[0], rf[1]);
                mma_f16(s1, qf[ks], rf[2], rf[3]);
            }
            int c0 = kt * 128 + jj * 16 + 2 * t;
            float pg0 = (c0 < TT)     ? __expf(s0[0] * RSQRT128 - Mq0) : 0.f;
            float pg1 = (c0 + 1 < TT) ? __expf(s0[1] * RSQRT128 - Mq0) : 0.f;
            float ph0 = (c0 < TT)     ? __expf(s0[2] * RSQRT128 - Mq1) : 0.f;
            float ph1 = (c0 + 1 < TT) ? __expf(s0[3] * RSQRT128 - Mq1) : 0.f;
            float pg8 = (c0 + 8 < TT) ? __expf(s1[0] * RSQRT128 - Mq0) : 0.f;
            float pg9 = (c0 + 9 < TT) ? __expf(s1[1] * RSQRT128 - Mq0) : 0.f;
            float ph8 = (c0 + 8 < TT) ? __expf(s1[2] * RSQRT128 - Mq1) : 0.f;
            float ph9 = (c0 + 9 < TT) ? __expf(s1[3] * RSQRT128 - Mq1) : 0.f;
            __nv_bfloat162 t0 = __floats2bfloat162_rn(pg0, pg1);
            __nv_bfloat162 t1 = __floats2bfloat162_rn(ph0, ph1);
            __nv_bfloat162 t2 = __floats2bfloat162_rn(pg8, pg9);
            __nv_bfloat162 t3 = __floats2bfloat162_rn(ph8, ph9);
            pf[jj][0] = *(uint32_t*)&t0;
            pf[jj][1] = *(uint32_t*)&t1;
            pf[jj][2] = *(uint32_t*)&t2;
            pf[jj][3] = *(uint32_t*)&t3;
            // row sums from ROUNDED P values (cancellation in ctx ratio)
            lsum0 += __bfloat162float(t0.x) + __bfloat162float(t0.y)
                   + __bfloat162float(t2.x) + __bfloat162float(t2.y);
            lsum1 += __bfloat162float(t1.x) + __bfloat162float(t1.y)
                   + __bfloat162float(t3.x) + __bfloat162float(t3.y);
        }

        // ---- ctx += P * (Vhi + Vlo), bf16, streaming ----
        #pragma unroll
        for (int kk = 0; kk < 8; kk++) {
            uint32_t vbase = vwo + (uint32_t)(kk * 16) * ROWB;
            #pragma unroll
            for (int d = 0; d < 8; d++) {
                uint32_t vh[4], vl[4];
                ldsm_x4t(vh, KH + vbase + d * 32);
                ldsm_x4t(vl, KL + vbase + d * 32);
                mma_bf16(cc[2 * d],     pf[kk], vh[0], vh[1]);
                mma_bf16(cc[2 * d],     pf[kk], vl[0], vl[1]);
                mma_bf16(cc[2 * d + 1], pf[kk], vh[2], vh[3]);
                mma_bf16(cc[2 * d + 1], pf[kk], vl[2], vl[3]);
            }
        }
        __syncthreads();
    }

    lsum0 += __shfl_xor_sync(0xffffffffu, lsum0, 1);
    lsum0 += __shfl_xor_sync(0xffffffffu, lsum0, 2);
    lsum1 += __shfl_xor_sync(0xffffffffu, lsum1, 1);
    lsum1 += __shfl_xor_sync(0xffffffffu, lsum1, 2);
    float inv0 = 1.f / lsum0, inv1 = 1.f / lsum1;

    #pragma unroll
    for (int d = 0; d < 16; d++) {
        if (row0 < TT) {
            float2 v = make_float2(cc[d][0] * inv0, cc[d][1] * inv0);
            *(float2*)(g_ctx + ((size_t)b * TT + row0) * DH + d * 8 + 2 * t) = v;
        }
        if (row0 + 8 < TT) {
            float2 v = make_float2(cc[d][2] * inv1, cc[d][3] * inv1);
            *(float2*)(g_ctx + ((size_t)b * TT + row0 + 8) * DH + d * 8 + 2 * t) = v;
        }
    }
}

// ---------------- segmented max/mean pooling (+ zero pre1) ----------------
__global__ void k_pool() {
    if (blockIdx.x < 256) g_pre1[blockIdx.x * 128 + threadIdx.x] = 0.f;
    int b = blockIdx.x / SNAPC;
    int s = blockIdx.x % SNAPC;
    int d = threadIdx.x;
    size_t base = ((size_t)b * TT + s * SEGC) * DH + d;
    float mx1 = -1e30f, sm1 = 0.f, mx2 = -1e30f, sm2 = 0.f;
    for (int i = 0; i < SEGC; i++) {
        float v1 = g_h1[base + (size_t)i * DH];
        mx1 = fmaxf(mx1, v1); sm1 += v1;
        float v2 = g_ctx[base + (size_t)i * DH];
        mx2 = fmaxf(mx2, v2); sm2 += v2;
    }
    int o = b * 6144 + s * 512 + d;
    const float inv = 1.f / (float)SEGC;
    g_feat[o]       = mx1;
    g_feat[o + 128] = sm1 * inv;
    g_feat[o + 256] = mx2;
    g_feat[o + 384] = sm2 * inv;
}

// ---------------- MLP1 (split-K) ----------------
__global__ void k_mlp1(const float* __restrict__ wf1) {
    __shared__ float As[64][65];
    __shared__ float Bs[64][64];
    int tid = threadIdx.x;
    int tx = tid % 16, ty = tid / 16;
    int col0 = blockIdx.x * 64;
    int kbase = blockIdx.y * 512;
    float acc[4][4];
    #pragma unroll
    for (int i = 0; i < 4; i++)
        #pragma unroll
        for (int j = 0; j < 4; j++) acc[i][j] = 0.f;

    for (int kc = 0; kc < 8; kc++) {
        int kb = kbase + kc * 64;
        for (int lin = tid; lin < 4096; lin += 256) {
            int i = lin >> 6, j = lin & 63;
            As[i][j] = g_feat[i * 6144 + kb + j];
        }
        for (int lin = tid; lin < 4096; lin += 256) {
            int r = lin >> 6, c = lin & 63;
            Bs[r][c] = wf1[(size_t)(kb + r) * 512 + col0 + c];
        }
        __syncthreads();
        #pragma unroll 4
        for (int k = 0; k < 64; k++) {
            float a[4], bb[4];
            #pragma unroll
            for (int i = 0; i < 4; i++) a[i] = As[ty * 4 + i][k];
            #pragma unroll
            for (int j = 0; j < 4; j++) bb[j] = Bs[k][tx * 4 + j];
            #pragma unroll
            for (int i = 0; i < 4; i++)
                #pragma unroll
                for (int j = 0; j < 4; j++) acc[i][j] += a[i] * bb[j];
        }
        __syncthreads();
    }
    #pragma unroll
    for (int i = 0; i < 4; i++)
        #pragma unroll
        for (int j = 0; j < 4; j++)
            atomicAdd(&g_pre1[(ty * 4 + i) * 512 + col0 + tx * 4 + j], acc[i][j]);
}

// ---------------- BN1 ----------------
__global__ void k_bn1(const float* __restrict__ bf1, const float* __restrict__ g1,
                      const float* __restrict__ be1) {
    int c = blockIdx.x * blockDim.x + threadIdx.x;
    if (c >= 512) return;
    float bias = bf1[c];
    float s = 0.f, s2 = 0.f;
    for (int r = 0; r < 64; r++) {
        float v = g_pre1[r * 512 + c] + bias;
        v = v / (1.f + __expf(-v));
        s += v; s2 += v * v;
    }
    float mu = s * (1.f / 64.f);
    float var = s2 * (1.f / 64.f) - mu * mu;
    float sc = g1[c] * rsqrtf(var + 1e-5f);
    float sh = be1[c] - mu * sc;
    for (int r = 0; r < 64; r++) {
        float v = g_pre1[r * 512 + c] + bias;
        v = v / (1.f + __expf(-v));
        g_out1[r * 512 + c] = v * sc + sh;
    }
}

// ---------------- MLP2 ----------------
__global__ void k_mlp2(const float* __restrict__ wf2, const float* __restrict__ bf2) {
    int tid = threadIdx.x;
    int c = tid % 32;
    int r = blockIdx.x * 4 + tid / 32;
    const float* orow = g_out1 + r * 512;
    float acc = 0.f;
    for (int k = 0; k < 512; k++) acc += orow[k] * wf2[k * 32 + c];
    acc += bf2[c];
    g_pre2[r * 32 + c] = acc / (1.f + __expf(-acc));
}

// ---------------- head ----------------
__global__ void k_head(const float* __restrict__ g2, const float* __restrict__ be2,
                       const float* __restrict__ wf3, const float* __restrict__ bf3,
                       float* __restrict__ out) {
    __shared__ float sh[64 * 32];
    __shared__ float scale_s[32], shift_s[32];
    int tid = threadIdx.x;
    for (int i = tid; i < 2048; i += 256) sh[i] = g_pre2[i];
    __syncthreads();
    if (tid < 32) {
        int c = tid;
        float s = 0.f, s2 = 0.f;
        for (int r = 0; r < 64; r++) { float v = sh[r * 32 + c]; s += v; s2 += v * v; }
        float mu = s * (1.f / 64.f);
        float var = s2 * (1.f / 64.f) - mu * mu;
        float sc = g2[c] * rsqrtf(var + 1e-5f);
        scale_s[c] = sc;
        shift_s[c] = be2[c] - mu * sc;
    }
    __syncthreads();
    if (tid < 64) {
        int r = tid;
        float l0 = bf3[0], l1 = bf3[1];
        for (int c = 0; c < 32; c++) {
            float h = sh[r * 32 + c] * scale_s[c] + shift_s[c];
            l0 += h * wf3[c * 2];
            l1 += h * wf3[c * 2 + 1];
        }
        float m = fmaxf(l0, l1);
        float e0 = __expf(l0 - m), e1 = __expf(l1 - m);
        float inv = 1.f / (e0 + e1);
        out[r * 2]     = e0 * inv;
        out[r * 2 + 1] = e1 * inv;
    }
}

// ---------------- launcher ----------------
extern "C" void kernel_launch(void* const* d_in, const int* in_sizes, int n_in,
                              void* d_out, int out_size) {
    const float* x   = (const float*)d_in[0];
    const int*   ei  = (const int*)d_in[1];
    const float* w1  = (const float*)d_in[2];
    const float* b1  = (const float*)d_in[3];
    const float* w2  = (const float*)d_in[4];
    const float* b2  = (const float*)d_in[5];
    const float* pe  = (const float*)d_in[6];
    const float* wf1 = (const float*)d_in[7];
    const float* bf1 = (const float*)d_in[8];
    const float* g1  = (const float*)d_in[9];
    const float* be1 = (const float*)d_in[10];
    const float* wf2 = (const float*)d_in[11];
    const float* bf2 = (const float*)d_in[12];
    const float* g2  = (const float*)d_in[13];
    const float* be2 = (const float*)d_in[14];
    const float* wf3 = (const float*)d_in[15];
    const float* bf3 = (const float*)d_in[16];
    float* out = (float*)d_out;

    const int ATTN_SMEM = 6 * 128 * ROWB;    // 208896 (2x triple buffers: fp16 K + bf16 V hi/lo)
    const int G1_SMEM   = 6 * 128 * ROWB1;   // 159744
    const int G2_SMEM   = 6 * 128 * ROWB;    // 208896
    static int attr_set = 0;
    if (!attr_set) {
        cudaFuncSetAttribute(k_attn_mma, cudaFuncAttributeMaxDynamicSharedMemorySize,
                             ATTN_SMEM);
        cudaFuncSetAttribute(k_gemm1_mma, cudaFuncAttributeMaxDynamicSharedMemorySize,
                             G1_SMEM);
        cudaFuncSetAttribute(k_gemm2_mma, cudaFuncAttributeMaxDynamicSharedMemorySize,
                             G2_SMEM);
        attr_set = 1;
    }

    k_init<<<252, 256>>>(ei, w1, w2);                 // 1
    k_fill<<<EE / 256, 256>>>(ei);                    // 2
    k_agg1<<<NN / 8, 256>>>(x);                       // 3
    k_gemm1_mma<<<126, 256, G1_SMEM>>>(b1);           // 4 <- profiled slot (clock sentinel)
    k_agg2<<<NN / 8, 256>>>();                        // 5
    k_gemm2_mma<<<126, 256, G2_SMEM>>>(b2, pe);       // 6
    k_attn_mma<<<dim3(8, BB), 256, ATTN_SMEM>>>();    // 7
    k_pool<<<BB * SNAPC, 128>>>();                    // 8
    k_mlp1<<<dim3(8, 12), 256>>>(wf1);                // 9
    k_bn1<<<2, 256>>>(bf1, g1, be1);                  // 10
    k_mlp2<<<16, 128>>>(wf2, bf2);                    // 11
    k_head<<<1, 256>>>(g2, be2, wf3, bf3, out);       // 12
}